// round 15
// baseline (speedup 1.0000x reference)
#include <cuda_runtime.h>
#include <math.h>
#include <cstdint>

#define D 256
#define T_ 1024
#define NN 64
#define ROWS 65536   // T_*NN
#define M 64

// output layout (concatenated, fp32)
#define OFF_UQ 0UL                  // (512,1024,64) = 33554432
#define OFF_UM 33554432UL           // (64,256)      = 16384
#define OFF_SQ 33570816UL           // (65536,64)    = 4194304
#define OFF_SM 37765120UL           // (65536,64)    = 4194304
#define OFF_SP 41959424UL           // (65536,)      = 65536
#define OFF_GL 42024960UL           // (65536,256)   = 16777216

typedef unsigned long long ull;

// ---------------- scratch (static device globals; no allocations) ------------
__device__ float g_keysT[D * M];        // keys transposed [d][m]
__constant__ float4 cK4[D * M / 4];     // 64 KB: keysT as float4 [d][j], j<16
__device__ float g_knorm[M];            // ||k_m||^2
__device__ float g_ksum[M];             // sum_d k_m[d]
__device__ float g_bmax[256 * M];       // per-block column max partials
__device__ float g_bsum[256 * M];       // per-block column sum partials (vs bmax)
__device__ float g_cmax[M];
__device__ float g_csum[M];
__device__ float g_sval[ROWS];          // row max = score at top1
__device__ float g_se[ROWS];            // row sum of exp(s - rowmax)
__device__ int   g_top1[ROWS];
__device__ int   g_top2i[ROWS];
__device__ float g_qupd[M * D];

// ---------------- scalar helpers ---------------------------------------------
__device__ __forceinline__ ull pack2(float lo, float hi) {
    ull r; asm("mov.b64 %0, {%1, %2};" : "=l"(r) : "f"(lo), "f"(hi)); return r;
}
__device__ __forceinline__ void unpack2(ull v, float& lo, float& hi) {
    asm("mov.b64 {%0, %1}, %2;" : "=f"(lo), "=f"(hi) : "l"(v));
}
__device__ __forceinline__ ull fma2(ull a, ull b, ull c) {
    ull d; asm("fma.rn.f32x2 %0, %1, %2, %3;" : "=l"(d) : "l"(a), "l"(b), "l"(c));
    return d;
}

// ---------------- K0a: keys transpose + zero qupd ------------------------------
__global__ __launch_bounds__(256) void k0a_init(const float* __restrict__ keys) {
    const int b = blockIdx.x;          // memory slot m
    const int t = threadIdx.x;         // d
    g_keysT[t * M + b] = keys[b * 256 + t];
    g_qupd[b * 256 + t] = 0.0f;
}

// ---------------- K0b: key norms -----------------------------------------------
__global__ __launch_bounds__(256) void k0b_norm(const float* __restrict__ keys) {
    __shared__ float rn[8];
    const int b = blockIdx.x, t = threadIdx.x;
    const int lane = t & 31, w = t >> 5;
    float kv = keys[b * 256 + t];
    float n2 = kv * kv;
#pragma unroll
    for (int off = 16; off > 0; off >>= 1) n2 += __shfl_xor_sync(0xffffffffu, n2, off);
    if (lane == 0) rn[w] = n2;
    __syncthreads();
    if (t == 0) {
        float tn = 0.0f;
#pragma unroll
        for (int i = 0; i < 8; ++i) tn += rn[i];
        g_knorm[b] = tn;
    }
}

// ---------------- K0c: key sums -------------------------------------------------
__global__ __launch_bounds__(256) void k0c_sum(const float* __restrict__ keys) {
    __shared__ float rs[8];
    const int b = blockIdx.x, t = threadIdx.x;
    const int lane = t & 31, w = t >> 5;
    float kv = keys[b * 256 + t];
#pragma unroll
    for (int off = 16; off > 0; off >>= 1) kv += __shfl_xor_sync(0xffffffffu, kv, off);
    if (lane == 0) rs[w] = kv;
    __syncthreads();
    if (t == 0) {
        float ts = 0.0f;
#pragma unroll
        for (int i = 0; i < 8; ++i) ts += rs[i];
        g_ksum[b] = ts;
    }
}

// ---------------- K1: score GEMM (const-mem) + softmaxes + concat GEMM (smem) -
__global__ __launch_bounds__(256, 2) void k1_score(const float* __restrict__ q,
                                                   float* __restrict__ out_sm,
                                                   float* __restrict__ out_uq,
                                                   float* __restrict__ out_sp) {
    __shared__ float sK[D * M];        // 64 KB keysT [d][m] (for concat GEMM)
    __shared__ float wred[8 * 64];
    __shared__ float bmaxs[64];
    __shared__ float sKn[64], sKs[64];
    const int tid = threadIdx.x;
    const int row = blockIdx.x * 256 + tid;
    const int lane = tid & 31, wid = tid >> 5;

    {   // stage keysT to SMEM (coalesced)
        const float4* src = (const float4*)g_keysT;
        float4* dst = (float4*)sK;
#pragma unroll
        for (int i = 0; i < 16; ++i) dst[i * 256 + tid] = src[i * 256 + tid];
        if (tid < 64) { sKn[tid] = g_knorm[tid]; sKs[tid] = g_ksum[tid]; }
    }
    __syncthreads();

    float s[64];
#pragma unroll
    for (int j = 0; j < 64; ++j) s[j] = 0.0f;
    float nq2 = 0.0f, sumq = 0.0f;

    // ---- score GEMM: keys from CONSTANT memory (separate port, L1 untouched)
    for (int d0 = 0; d0 < D; d0 += 8) {
        float qv[8];
#pragma unroll
        for (int u = 0; u < 8; ++u) qv[u] = __ldg(&q[(d0 + u) * ROWS + row]);
#pragma unroll
        for (int u = 0; u < 8; ++u) {      // free updated_query[:256] copy (streaming)
            __stcs(&out_uq[(size_t)(d0 + u) * ROWS + row], qv[u]);
            nq2 = fmaf(qv[u], qv[u], nq2);
            sumq += qv[u];
        }
#pragma unroll
        for (int u = 0; u < 8; ++u) {
#pragma unroll
            for (int j = 0; j < 16; ++j) {
                float4 kc = cK4[(d0 + u) * 16 + j];
                s[4 * j]     = fmaf(qv[u], kc.x, s[4 * j]);
                s[4 * j + 1] = fmaf(qv[u], kc.y, s[4 * j + 1]);
                s[4 * j + 2] = fmaf(qv[u], kc.z, s[4 * j + 2]);
                s[4 * j + 3] = fmaf(qv[u], kc.w, s[4 * j + 3]);
            }
        }
    }

    // top-2 (strict > keeps lowest index on ties, matching lax.top_k)
    float v1 = -1e30f, v2 = -1e30f; int i1 = 0, i2 = 0;
#pragma unroll
    for (int m = 0; m < 64; ++m) {
        float v = s[m];
        if (v > v1) { v2 = v1; i2 = i1; v1 = v; i1 = m; }
        else if (v > v2) { v2 = v; i2 = m; }
    }
    g_top1[row] = i1;
    g_top2i[row] = i2;
    g_sval[row] = v1;

    // spreading_loss via algebraic identity:
    // ||q - k + e||^2 = ||q||^2 - 2 s + ||k||^2 + 2e(sum q - sum k) + 256 e^2
    {
        const float e = 1e-6f;
        float dp2 = nq2 - 2.0f * v1 + sKn[i1] + 2.0f * e * (sumq - sKs[i1]) + 256.0f * e * e;
        float dn2 = nq2 - 2.0f * v2 + sKn[i2] + 2.0f * e * (sumq - sKs[i2]) + 256.0f * e * e;
        out_sp[row] = fmaxf(sqrtf(fmaxf(dp2, 0.0f)) - sqrtf(fmaxf(dn2, 0.0f)) + 1.0f, 0.0f);
    }

    // block column-max partials
#pragma unroll
    for (int m = 0; m < 64; ++m) {
        float v = s[m];
        v = fmaxf(v, __shfl_xor_sync(0xffffffffu, v, 16));
        v = fmaxf(v, __shfl_xor_sync(0xffffffffu, v, 8));
        v = fmaxf(v, __shfl_xor_sync(0xffffffffu, v, 4));
        v = fmaxf(v, __shfl_xor_sync(0xffffffffu, v, 2));
        v = fmaxf(v, __shfl_xor_sync(0xffffffffu, v, 1));
        if (lane == 0) wred[wid * 64 + m] = v;
    }
    __syncthreads();
    if (tid < 64) {
        float mx = wred[tid];
#pragma unroll
        for (int w = 1; w < 8; ++w) mx = fmaxf(mx, wred[w * 64 + tid]);
        bmaxs[tid] = mx;
        g_bmax[blockIdx.x * 64 + tid] = mx;
    }
    __syncthreads();

    // block column-sum partials w.r.t. block max (online softmax merge later)
#pragma unroll
    for (int m = 0; m < 64; ++m) {
        float c = __expf(s[m] - bmaxs[m]);
        c += __shfl_xor_sync(0xffffffffu, c, 16);
        c += __shfl_xor_sync(0xffffffffu, c, 8);
        c += __shfl_xor_sync(0xffffffffu, c, 4);
        c += __shfl_xor_sync(0xffffffffu, c, 2);
        c += __shfl_xor_sync(0xffffffffu, c, 1);
        if (lane == 0) wred[wid * 64 + m] = c;
    }
    __syncthreads();
    if (tid < 64) {
        float sm = 0.0f;
#pragma unroll
        for (int w = 0; w < 8; ++w) sm += wred[w * 64 + tid];
        g_bsum[blockIdx.x * 64 + tid] = sm;
    }

    // row softmax -> probabilities (== score_memory row)
    float se = 0.0f;
#pragma unroll
    for (int m = 0; m < 64; ++m) { s[m] = __expf(s[m] - v1); se += s[m]; }
    g_se[row] = se;
    float inv = 1.0f / se;
#pragma unroll
    for (int m = 0; m < 64; ++m) s[m] *= inv;
#pragma unroll
    for (int j = 0; j < 16; ++j) {
        float4 t = make_float4(s[4 * j], s[4 * j + 1], s[4 * j + 2], s[4 * j + 3]);
        ((float4*)(out_sm + (size_t)row * 64))[j] = t;   // sm IS re-read -> keep in L2
    }

    // ---- fused concat_memory GEMM: updated_query[256:] = P @ keys (SMEM+fma2)
    ull p2[32];
#pragma unroll
    for (int j = 0; j < 32; ++j) p2[j] = pack2(s[2 * j], s[2 * j + 1]);

    const ulonglong2* ks2 = (const ulonglong2*)sK;
#pragma unroll 4
    for (int d = 0; d < D; ++d) {
        ull a0 = 0ull, a1 = 0ull;
#pragma unroll
        for (int jj = 0; jj < 16; ++jj) {
            ulonglong2 kk = ks2[d * 16 + jj];
            a0 = fma2(p2[2 * jj],     kk.x, a0);
            a1 = fma2(p2[2 * jj + 1], kk.y, a1);
        }
        float l0, h0, l1, h1;
        unpack2(a0, l0, h0); unpack2(a1, l1, h1);
        __stcs(&out_uq[(size_t)(256 + d) * ROWS + row], (l0 + h0) + (l1 + h1));
    }
}

// ---------------- K2: combine per-block partials ------------------------------
__global__ __launch_bounds__(256) void k2_combine() {   // grid 64 (one per m)
    __shared__ float red[256];
    const int m = blockIdx.x, t = threadIdx.x;
    float bm = g_bmax[t * 64 + m];
    red[t] = bm;
    __syncthreads();
#pragma unroll
    for (int s = 128; s > 0; s >>= 1) {
        if (t < s) red[t] = fmaxf(red[t], red[t + s]);
        __syncthreads();
    }
    float cmax = red[0];
    __syncthreads();
    red[t] = g_bsum[t * 64 + m] * __expf(bm - cmax);
    __syncthreads();
#pragma unroll
    for (int s = 128; s > 0; s >>= 1) {
        if (t < s) red[t] += red[t + s];
        __syncthreads();
    }
    if (t == 0) { g_cmax[m] = cmax; g_csum[m] = red[0]; }
}

// ---------------- K3: score_query reconstructed from score_memory -------------
// sq[r][m] = sm[r][m] * se_r * exp(v1_r - cmax_m) / csum_m
__global__ __launch_bounds__(256) void k3_sq(const float* __restrict__ sm_in,
                                             float* __restrict__ out_sq) {
    __shared__ float cm[64], iv[64];
    const int tid = threadIdx.x;
    if (tid < 64) { cm[tid] = g_cmax[tid]; iv[tid] = 1.0f / g_csum[tid]; }
    __syncthreads();
    const float4* src = (const float4*)sm_in;
    float4* dst = (float4*)out_sq;
    const int base = blockIdx.x * 256 + tid;   // grid 1024 -> 262144 threads
#pragma unroll
    for (int r = 0; r < 4; ++r) {
        int i4 = base + r * 262144;
        int row = i4 >> 4;
        float v1 = __ldg(&g_sval[row]);
        float se = __ldg(&g_se[row]);
        int m0 = (i4 << 2) & 63;
        float4 v = src[i4];
        float4 o;
        o.x = v.x * se * __expf(v1 - cm[m0])     * iv[m0];
        o.y = v.y * se * __expf(v1 - cm[m0 + 1]) * iv[m0 + 1];
        o.z = v.z * se * __expf(v1 - cm[m0 + 2]) * iv[m0 + 2];
        o.w = v.w * se * __expf(v1 - cm[m0 + 3]) * iv[m0 + 3];
        __stcs(&dst[i4], o);
    }
}

// ---------------- K4f: gathering_loss + query_update scatter (fused) ----------
// grid 512 x 128 rows; warp w owns memories [8w, 8w+8); lane covers d = lane+32i.
__global__ __launch_bounds__(256, 2) void k4_fused(const float* __restrict__ q,
                                                   const float* __restrict__ keys,
                                                   float* __restrict__ out_gl) {
    __shared__ float tile[256 * 33];   // [d][r]
    __shared__ int   gi[32];
    __shared__ float swgt[32];
    __shared__ float scm[64];

    const int tid = threadIdx.x;
    const int lane = tid & 31, w = tid >> 5;
    const int rowbase = blockIdx.x * 128;

    if (tid < 64) scm[tid] = g_cmax[tid];

    float acc[8][8];   // [mi][i]
#pragma unroll
    for (int mi = 0; mi < 8; ++mi)
#pragma unroll
        for (int i = 0; i < 8; ++i) acc[mi][i] = 0.0f;

    for (int c = 0; c < 4; ++c) {
        const int row0 = rowbase + c * 32;
        __syncthreads();   // previous chunk's readers done; scm ready (c==0)
        if (tid < 32) {
            int g = g_top1[row0 + tid];
            gi[tid] = g;
            swgt[tid] = __expf(g_sval[row0 + tid] - scm[g]);
        }
        // phase A: coalesced load of 32x256 q chunk into [d][r] tile
        {
            const int r = lane, dg = w;
#pragma unroll 8
            for (int it = 0; it < 32; ++it) {
                int d = it * 8 + dg;
                tile[d * 33 + r] = q[(size_t)d * ROWS + row0 + r];
            }
        }
        __syncthreads();

        // phase B: gathering_loss only (d = tid across threads, coalesced)
        const int d = tid;
#pragma unroll 4
        for (int it = 0; it < 32; ++it) {
            int g = gi[it];
            float qv = tile[d * 33 + it];
            float kp = __ldg(&keys[g * 256 + d]);
            float df = qv - kp;
            __stcs(&out_gl[(size_t)(row0 + it) * 256 + d], df * df);
        }

        // phase C: warp-owned scatter-reduce into registers
        for (int r = 0; r < 32; ++r) {
            int g = gi[r];
            if ((g >> 3) == w) {
                float wv = swgt[r];
#pragma unroll
                for (int mi = 0; mi < 8; ++mi) {
                    if (g == w * 8 + mi) {
#pragma unroll
                        for (int i = 0; i < 8; ++i)
                            acc[mi][i] += wv * tile[(lane + 32 * i) * 33 + r];
                    }
                }
            }
        }
    }

    // epilogue: one global reduce per (m, d)
#pragma unroll
    for (int mi = 0; mi < 8; ++mi)
#pragma unroll
        for (int i = 0; i < 8; ++i)
            atomicAdd(&g_qupd[(w * 8 + mi) * 256 + lane + 32 * i], acc[mi][i]);
}

// ---------------- K7: updated_memory = normalize(qupd + keys) -----------------
__global__ __launch_bounds__(256) void k7_um(const float* __restrict__ keys,
                                             float* __restrict__ out_um) {
    __shared__ float wr[8];
    const int m = blockIdx.x, d = threadIdx.x;
    const int lane = d & 31, w = d >> 5;
    float val = g_qupd[m * 256 + d] + keys[m * 256 + d];
    float ss = val * val;
#pragma unroll
    for (int off = 16; off > 0; off >>= 1) ss += __shfl_xor_sync(0xffffffffu, ss, off);
    if (lane == 0) wr[w] = ss;
    __syncthreads();
    float tot = 0.0f;
#pragma unroll
    for (int i = 0; i < 8; ++i) tot += wr[i];
    float n = sqrtf(tot);
    float denom = fmaxf(n, 1e-12f);
    out_um[m * 256 + d] = val / denom;
}

// ---------------- launch -------------------------------------------------------
extern "C" void kernel_launch(void* const* d_in, const int* in_sizes, int n_in,
                              void* d_out, int out_size) {
    const float* query = (const float*)d_in[0];   // (256, 1024, 64)
    const float* keys  = (const float*)d_in[1];   // (64, 256)
    float* out = (float*)d_out;

    // resolve symbol addresses (pure queries, not stream ops)
    void* cK4_addr = nullptr;
    void* keysT_addr = nullptr;
    cudaGetSymbolAddress(&cK4_addr, cK4);
    cudaGetSymbolAddress(&keysT_addr, g_keysT);

    k0a_init<<<64, 256>>>(keys);
    // fill constant bank from g_keysT (D2D async memcpy: graph-capturable)
    cudaMemcpyAsync(cK4_addr, keysT_addr, D * M * sizeof(float),
                    cudaMemcpyDeviceToDevice);
    k0b_norm<<<64, 256>>>(keys);
    k0c_sum<<<64, 256>>>(keys);
    k1_score<<<256, 256>>>(query, out + OFF_SM, out + OFF_UQ, out + OFF_SP);
    k2_combine<<<64, 256>>>();
    k3_sq<<<1024, 256>>>(out + OFF_SM, out + OFF_SQ);
    k4_fused<<<512, 256>>>(query, keys, out + OFF_GL);
    k7_um<<<64, 256>>>(keys, out + OFF_UM);
}

// round 16
// speedup vs baseline: 1.0328x; 1.0328x over previous
#include <cuda_runtime.h>
#include <math.h>
#include <cstdint>

#define D 256
#define T_ 1024
#define NN 64
#define ROWS 65536   // T_*NN
#define M 64

// output layout (concatenated, fp32)
#define OFF_UQ 0UL                  // (512,1024,64) = 33554432
#define OFF_UM 33554432UL           // (64,256)      = 16384
#define OFF_SQ 33570816UL           // (65536,64)    = 4194304
#define OFF_SM 37765120UL           // (65536,64)    = 4194304
#define OFF_SP 41959424UL           // (65536,)      = 65536
#define OFF_GL 42024960UL           // (65536,256)   = 16777216

typedef unsigned long long ull;

// ---------------- scratch (static device globals; no allocations) ------------
__device__ float g_keysT[D * M];        // keys transposed [d][m]
__device__ float g_knorm[M];            // ||k_m||^2
__device__ float g_ksum[M];             // sum_d k_m[d]
__device__ float g_bmax[128 * M];       // per-block column max partials (128 blocks)
__device__ float g_bsum[128 * M];       // per-block column sum partials (vs bmax)
__device__ float g_cmax[M];
__device__ float g_csum[M];
__device__ float g_sval[ROWS];          // row max = score at top1
__device__ float g_se[ROWS];            // row sum of exp(s - rowmax)
__device__ int   g_top1[ROWS];
__device__ int   g_top2i[ROWS];
__device__ float g_qupd[M * D];

// ---------------- scalar helpers ---------------------------------------------
__device__ __forceinline__ ull pack2(float lo, float hi) {
    ull r; asm("mov.b64 %0, {%1, %2};" : "=l"(r) : "f"(lo), "f"(hi)); return r;
}
__device__ __forceinline__ void unpack2(ull v, float& lo, float& hi) {
    asm("mov.b64 {%0, %1}, %2;" : "=f"(lo), "=f"(hi) : "l"(v));
}
__device__ __forceinline__ ull fma2(ull a, ull b, ull c) {
    ull d; asm("fma.rn.f32x2 %0, %1, %2, %3;" : "=l"(d) : "l"(a), "l"(b), "l"(c));
    return d;
}
__device__ __forceinline__ ull add2(ull a, ull b) {
    ull d; asm("add.rn.f32x2 %0, %1, %2;" : "=l"(d) : "l"(a), "l"(b));
    return d;
}

// ---------------- K0a: keys transpose + zero qupd ------------------------------
__global__ __launch_bounds__(256) void k0a_init(const float* __restrict__ keys) {
    const int b = blockIdx.x;          // memory slot m
    const int t = threadIdx.x;         // d
    g_keysT[t * M + b] = keys[b * 256 + t];
    g_qupd[b * 256 + t] = 0.0f;
}

// ---------------- K0b: key norms -----------------------------------------------
__global__ __launch_bounds__(256) void k0b_norm(const float* __restrict__ keys) {
    __shared__ float rn[8];
    const int b = blockIdx.x, t = threadIdx.x;
    const int lane = t & 31, w = t >> 5;
    float kv = keys[b * 256 + t];
    float n2 = kv * kv;
#pragma unroll
    for (int off = 16; off > 0; off >>= 1) n2 += __shfl_xor_sync(0xffffffffu, n2, off);
    if (lane == 0) rn[w] = n2;
    __syncthreads();
    if (t == 0) {
        float tn = 0.0f;
#pragma unroll
        for (int i = 0; i < 8; ++i) tn += rn[i];
        g_knorm[b] = tn;
    }
}

// ---------------- K0c: key sums -------------------------------------------------
__global__ __launch_bounds__(256) void k0c_sum(const float* __restrict__ keys) {
    __shared__ float rs[8];
    const int b = blockIdx.x, t = threadIdx.x;
    const int lane = t & 31, w = t >> 5;
    float kv = keys[b * 256 + t];
#pragma unroll
    for (int off = 16; off > 0; off >>= 1) kv += __shfl_xor_sync(0xffffffffu, kv, off);
    if (lane == 0) rs[w] = kv;
    __syncthreads();
    if (t == 0) {
        float ts = 0.0f;
#pragma unroll
        for (int i = 0; i < 8; ++i) ts += rs[i];
        g_ksum[b] = ts;
    }
}

// ---------------- K1: dual-row packed GEMMs + softmaxes + top2 + spreading ----
// Thread handles rows row0 = blk*512+tid and row1 = row0+256, packed in f32x2.
// Keys duplicated (k,k) in dynamic SMEM so every fma2 does dual-row work.
#define K1_SMEM (131072 + 512 * 4 + 64 * 4 * 3)
__global__ __launch_bounds__(256, 1) void k1_score(const float* __restrict__ q,
                                                   float* __restrict__ out_sm,
                                                   float* __restrict__ out_uq,
                                                   float* __restrict__ out_sp) {
    extern __shared__ char smem[];
    ull*   sKd   = (ull*)smem;                     // 128 KB: (k,k) duplicated [d][m]
    float* wred  = (float*)(smem + 131072);        // 8 warps x 64
    float* bmaxs = wred + 512;
    float* sKn   = bmaxs + 64;
    float* sKs   = sKn + 64;

    const int tid = threadIdx.x;
    const int row0 = blockIdx.x * 512 + tid;
    const int row1 = row0 + 256;
    const int lane = tid & 31, wid = tid >> 5;

    {   // stage duplicated keys (coalesced float reads, 8B coalesced stores)
#pragma unroll
        for (int i = 0; i < 64; ++i) {
            int idx = i * 256 + tid;
            float v = g_keysT[idx];
            sKd[idx] = pack2(v, v);
        }
        if (tid < 64) { sKn[tid] = g_knorm[tid]; sKs[tid] = g_ksum[tid]; }
    }
    __syncthreads();

    ull acc[64];
#pragma unroll
    for (int j = 0; j < 64; ++j) acc[j] = 0ull;
    ull nq2p = 0ull, sumqp = 0ull;
    const ull ones = pack2(1.0f, 1.0f);

    const ulonglong2* ks2 = (const ulonglong2*)sKd;

    for (int d0 = 0; d0 < D; d0 += 4) {
        ull q2[4];
#pragma unroll
        for (int u = 0; u < 4; ++u) {
            float qa = __ldg(&q[(d0 + u) * ROWS + row0]);
            float qb = __ldg(&q[(d0 + u) * ROWS + row1]);
            __stcs(&out_uq[(size_t)(d0 + u) * ROWS + row0], qa);
            __stcs(&out_uq[(size_t)(d0 + u) * ROWS + row1], qb);
            q2[u] = pack2(qa, qb);
        }
#pragma unroll
        for (int u = 0; u < 4; ++u) {
            nq2p  = fma2(q2[u], q2[u], nq2p);
            sumqp = fma2(q2[u], ones, sumqp);
#pragma unroll
            for (int jj = 0; jj < 32; ++jj) {
                ulonglong2 kk = ks2[(d0 + u) * 32 + jj];
                acc[2 * jj]     = fma2(q2[u], kk.x, acc[2 * jj]);
                acc[2 * jj + 1] = fma2(q2[u], kk.y, acc[2 * jj + 1]);
            }
        }
    }

    float s0[64], s1[64];
#pragma unroll
    for (int j = 0; j < 64; ++j) unpack2(acc[j], s0[j], s1[j]);
    float nq2a, nq2b, sma, smb;
    unpack2(nq2p, nq2a, nq2b);
    unpack2(sumqp, sma, smb);

    // top-2 per row (strict > keeps lowest index on ties, matching lax.top_k)
    float v1a = -1e30f, v2a = -1e30f; int i1a = 0, i2a = 0;
    float v1b = -1e30f, v2b = -1e30f; int i1b = 0, i2b = 0;
#pragma unroll
    for (int m = 0; m < 64; ++m) {
        float va = s0[m];
        if (va > v1a) { v2a = v1a; i2a = i1a; v1a = va; i1a = m; }
        else if (va > v2a) { v2a = va; i2a = m; }
        float vb = s1[m];
        if (vb > v1b) { v2b = v1b; i2b = i1b; v1b = vb; i1b = m; }
        else if (vb > v2b) { v2b = vb; i2b = m; }
    }
    g_top1[row0] = i1a;  g_top1[row1] = i1b;
    g_top2i[row0] = i2a; g_top2i[row1] = i2b;
    g_sval[row0] = v1a;  g_sval[row1] = v1b;

    // spreading_loss via identity: ||q-k+e||^2 = ||q||^2 - 2s + ||k||^2 + 2e(sq-sk) + 256e^2
    {
        const float e = 1e-6f;
        float dp2 = nq2a - 2.0f * v1a + sKn[i1a] + 2.0f * e * (sma - sKs[i1a]) + 256.0f * e * e;
        float dn2 = nq2a - 2.0f * v2a + sKn[i2a] + 2.0f * e * (sma - sKs[i2a]) + 256.0f * e * e;
        out_sp[row0] = fmaxf(sqrtf(fmaxf(dp2, 0.0f)) - sqrtf(fmaxf(dn2, 0.0f)) + 1.0f, 0.0f);
        dp2 = nq2b - 2.0f * v1b + sKn[i1b] + 2.0f * e * (smb - sKs[i1b]) + 256.0f * e * e;
        dn2 = nq2b - 2.0f * v2b + sKn[i2b] + 2.0f * e * (smb - sKs[i2b]) + 256.0f * e * e;
        out_sp[row1] = fmaxf(sqrtf(fmaxf(dp2, 0.0f)) - sqrtf(fmaxf(dn2, 0.0f)) + 1.0f, 0.0f);
    }

    // block column-max partials (combine both rows before shuffling)
#pragma unroll
    for (int m = 0; m < 64; ++m) {
        float v = fmaxf(s0[m], s1[m]);
        v = fmaxf(v, __shfl_xor_sync(0xffffffffu, v, 16));
        v = fmaxf(v, __shfl_xor_sync(0xffffffffu, v, 8));
        v = fmaxf(v, __shfl_xor_sync(0xffffffffu, v, 4));
        v = fmaxf(v, __shfl_xor_sync(0xffffffffu, v, 2));
        v = fmaxf(v, __shfl_xor_sync(0xffffffffu, v, 1));
        if (lane == 0) wred[wid * 64 + m] = v;
    }
    __syncthreads();
    if (tid < 64) {
        float mx = wred[tid];
#pragma unroll
        for (int w = 1; w < 8; ++w) mx = fmaxf(mx, wred[w * 64 + tid]);
        bmaxs[tid] = mx;
        g_bmax[blockIdx.x * 64 + tid] = mx;
    }
    __syncthreads();

    // block column-sum partials w.r.t. block max (both rows combined)
#pragma unroll
    for (int m = 0; m < 64; ++m) {
        float bm = bmaxs[m];
        float c = __expf(s0[m] - bm) + __expf(s1[m] - bm);
        c += __shfl_xor_sync(0xffffffffu, c, 16);
        c += __shfl_xor_sync(0xffffffffu, c, 8);
        c += __shfl_xor_sync(0xffffffffu, c, 4);
        c += __shfl_xor_sync(0xffffffffu, c, 2);
        c += __shfl_xor_sync(0xffffffffu, c, 1);
        if (lane == 0) wred[wid * 64 + m] = c;
    }
    __syncthreads();
    if (tid < 64) {
        float sm = 0.0f;
#pragma unroll
        for (int w = 0; w < 8; ++w) sm += wred[w * 64 + tid];
        g_bsum[blockIdx.x * 64 + tid] = sm;
    }

    // row softmaxes -> probabilities, store score_memory rows
    float sea = 0.0f, seb = 0.0f;
#pragma unroll
    for (int m = 0; m < 64; ++m) {
        s0[m] = __expf(s0[m] - v1a); sea += s0[m];
        s1[m] = __expf(s1[m] - v1b); seb += s1[m];
    }
    g_se[row0] = sea; g_se[row1] = seb;
    float inva = 1.0f / sea, invb = 1.0f / seb;
#pragma unroll
    for (int m = 0; m < 64; ++m) { s0[m] *= inva; s1[m] *= invb; }
#pragma unroll
    for (int j = 0; j < 16; ++j) {
        ((float4*)(out_sm + (size_t)row0 * 64))[j] =
            make_float4(s0[4 * j], s0[4 * j + 1], s0[4 * j + 2], s0[4 * j + 3]);
        ((float4*)(out_sm + (size_t)row1 * 64))[j] =
            make_float4(s1[4 * j], s1[4 * j + 1], s1[4 * j + 2], s1[4 * j + 3]);
    }

    // ---- fused concat GEMM: both rows per fma2 via duplicated keys ----
    ull pp[64];
#pragma unroll
    for (int m = 0; m < 64; ++m) pp[m] = pack2(s0[m], s1[m]);

#pragma unroll 2
    for (int d = 0; d < D; ++d) {
        ull a0 = 0ull, a1 = 0ull;
#pragma unroll
        for (int jj = 0; jj < 32; ++jj) {
            ulonglong2 kk = ks2[d * 32 + jj];
            a0 = fma2(pp[2 * jj],     kk.x, a0);
            a1 = fma2(pp[2 * jj + 1], kk.y, a1);
        }
        ull a = add2(a0, a1);
        float ra, rb;
        unpack2(a, ra, rb);
        __stcs(&out_uq[(size_t)(256 + d) * ROWS + row0], ra);
        __stcs(&out_uq[(size_t)(256 + d) * ROWS + row1], rb);
    }
}

// ---------------- K2: combine per-block partials (128 k1 blocks) --------------
__global__ __launch_bounds__(128) void k2_combine() {   // grid 64 (one per m)
    __shared__ float red[128];
    const int m = blockIdx.x, t = threadIdx.x;
    float bm = g_bmax[t * 64 + m];
    red[t] = bm;
    __syncthreads();
#pragma unroll
    for (int s = 64; s > 0; s >>= 1) {
        if (t < s) red[t] = fmaxf(red[t], red[t + s]);
        __syncthreads();
    }
    float cmax = red[0];
    __syncthreads();
    red[t] = g_bsum[t * 64 + m] * __expf(bm - cmax);
    __syncthreads();
#pragma unroll
    for (int s = 64; s > 0; s >>= 1) {
        if (t < s) red[t] += red[t + s];
        __syncthreads();
    }
    if (t == 0) { g_cmax[m] = cmax; g_csum[m] = red[0]; }
}

// ---------------- K3: score_query reconstructed from score_memory -------------
// sq[r][m] = sm[r][m] * se_r * exp(v1_r - cmax_m) / csum_m
__global__ __launch_bounds__(256) void k3_sq(const float* __restrict__ sm_in,
                                             float* __restrict__ out_sq) {
    __shared__ float cm[64], iv[64];
    const int tid = threadIdx.x;
    if (tid < 64) { cm[tid] = g_cmax[tid]; iv[tid] = 1.0f / g_csum[tid]; }
    __syncthreads();
    const float4* src = (const float4*)sm_in;
    float4* dst = (float4*)out_sq;
    const int base = blockIdx.x * 256 + tid;   // grid 1024 -> 262144 threads
#pragma unroll
    for (int r = 0; r < 4; ++r) {
        int i4 = base + r * 262144;
        int row = i4 >> 4;
        float v1 = __ldg(&g_sval[row]);
        float se = __ldg(&g_se[row]);
        int m0 = (i4 << 2) & 63;
        float4 v = src[i4];
        float4 o;
        o.x = v.x * se * __expf(v1 - cm[m0])     * iv[m0];
        o.y = v.y * se * __expf(v1 - cm[m0 + 1]) * iv[m0 + 1];
        o.z = v.z * se * __expf(v1 - cm[m0 + 2]) * iv[m0 + 2];
        o.w = v.w * se * __expf(v1 - cm[m0 + 3]) * iv[m0 + 3];
        __stcs(&dst[i4], o);
    }
}

// ---------------- K4f: gathering_loss + query_update scatter (fused) ----------
// grid 512 x 128 rows; warp w owns memories [8w, 8w+8); lane covers d = lane+32i.
__global__ __launch_bounds__(256, 2) void k4_fused(const float* __restrict__ q,
                                                   const float* __restrict__ keys,
                                                   float* __restrict__ out_gl) {
    __shared__ float tile[256 * 33];   // [d][r]
    __shared__ int   gi[32];
    __shared__ float swgt[32];
    __shared__ float scm[64];

    const int tid = threadIdx.x;
    const int lane = tid & 31, w = tid >> 5;
    const int rowbase = blockIdx.x * 128;

    if (tid < 64) scm[tid] = g_cmax[tid];

    float acc[8][8];   // [mi][i]
#pragma unroll
    for (int mi = 0; mi < 8; ++mi)
#pragma unroll
        for (int i = 0; i < 8; ++i) acc[mi][i] = 0.0f;

    for (int c = 0; c < 4; ++c) {
        const int row0 = rowbase + c * 32;
        __syncthreads();   // previous chunk's readers done; scm ready (c==0)
        if (tid < 32) {
            int g = g_top1[row0 + tid];
            gi[tid] = g;
            swgt[tid] = __expf(g_sval[row0 + tid] - scm[g]);
        }
        // phase A: coalesced load of 32x256 q chunk into [d][r] tile
        {
            const int r = lane, dg = w;
#pragma unroll 8
            for (int it = 0; it < 32; ++it) {
                int d = it * 8 + dg;
                tile[d * 33 + r] = q[(size_t)d * ROWS + row0 + r];
            }
        }
        __syncthreads();

        // phase B: gathering_loss only (d = tid across threads, coalesced)
        const int d = tid;
#pragma unroll 4
        for (int it = 0; it < 32; ++it) {
            int g = gi[it];
            float qv = tile[d * 33 + it];
            float kp = __ldg(&keys[g * 256 + d]);
            float df = qv - kp;
            __stcs(&out_gl[(size_t)(row0 + it) * 256 + d], df * df);
        }

        // phase C: warp-owned scatter-reduce into registers
        for (int r = 0; r < 32; ++r) {
            int g = gi[r];
            if ((g >> 3) == w) {
                float wv = swgt[r];
#pragma unroll
                for (int mi = 0; mi < 8; ++mi) {
                    if (g == w * 8 + mi) {
#pragma unroll
                        for (int i = 0; i < 8; ++i)
                            acc[mi][i] += wv * tile[(lane + 32 * i) * 33 + r];
                    }
                }
            }
        }
    }

    // epilogue: one global reduce per (m, d)
#pragma unroll
    for (int mi = 0; mi < 8; ++mi)
#pragma unroll
        for (int i = 0; i < 8; ++i)
            atomicAdd(&g_qupd[(w * 8 + mi) * 256 + lane + 32 * i], acc[mi][i]);
}

// ---------------- K7: updated_memory = normalize(qupd + keys) -----------------
__global__ __launch_bounds__(256) void k7_um(const float* __restrict__ keys,
                                             float* __restrict__ out_um) {
    __shared__ float wr[8];
    const int m = blockIdx.x, d = threadIdx.x;
    const int lane = d & 31, w = d >> 5;
    float val = g_qupd[m * 256 + d] + keys[m * 256 + d];
    float ss = val * val;
#pragma unroll
    for (int off = 16; off > 0; off >>= 1) ss += __shfl_xor_sync(0xffffffffu, ss, off);
    if (lane == 0) wr[w] = ss;
    __syncthreads();
    float tot = 0.0f;
#pragma unroll
    for (int i = 0; i < 8; ++i) tot += wr[i];
    float n = sqrtf(tot);
    float denom = fmaxf(n, 1e-12f);
    out_um[m * 256 + d] = val / denom;
}

// ---------------- launch -------------------------------------------------------
extern "C" void kernel_launch(void* const* d_in, const int* in_sizes, int n_in,
                              void* d_out, int out_size) {
    const float* query = (const float*)d_in[0];   // (256, 1024, 64)
    const float* keys  = (const float*)d_in[1];   // (64, 256)
    float* out = (float*)d_out;

    cudaFuncSetAttribute(k1_score, cudaFuncAttributeMaxDynamicSharedMemorySize, K1_SMEM);

    k0a_init<<<64, 256>>>(keys);
    k0b_norm<<<64, 256>>>(keys);
    k0c_sum<<<64, 256>>>(keys);
    k1_score<<<128, 256, K1_SMEM>>>(query, out + OFF_SM, out + OFF_UQ, out + OFF_SP);
    k2_combine<<<64, 128>>>();
    k3_sq<<<1024, 256>>>(out + OFF_SM, out + OFF_SQ);
    k4_fused<<<512, 256>>>(query, keys, out + OFF_GL);
    k7_um<<<64, 256>>>(keys, out + OFF_UM);
}

// round 17
// speedup vs baseline: 1.1164x; 1.0810x over previous
#include <cuda_runtime.h>
#include <math.h>
#include <cstdint>

#define D 256
#define T_ 1024
#define NN 64
#define ROWS 65536   // T_*NN
#define M 64

// output layout (concatenated, fp32)
#define OFF_UQ 0UL                  // (512,1024,64) = 33554432
#define OFF_UM 33554432UL           // (64,256)      = 16384
#define OFF_SQ 33570816UL           // (65536,64)    = 4194304
#define OFF_SM 37765120UL           // (65536,64)    = 4194304
#define OFF_SP 41959424UL           // (65536,)      = 65536
#define OFF_GL 42024960UL           // (65536,256)   = 16777216

typedef unsigned long long ull;

// ---------------- scratch (static device globals; no allocations) ------------
__device__ float g_keysT[D * M];        // keys transposed [d][m]
__device__ float g_knorm[M];            // ||k_m||^2
__device__ float g_ksum[M];             // sum_d k_m[d]
__device__ float g_bmax[256 * M];       // per-block column max partials
__device__ float g_bsum[256 * M];       // per-block column sum partials (vs bmax)
__device__ float g_cmax[M];
__device__ float g_csum[M];
__device__ float g_sval[ROWS];          // row max = score at top1
__device__ float g_sval2[ROWS];         // second-best score
__device__ float g_se[ROWS];            // row sum of exp(s - rowmax)
__device__ int   g_top1[ROWS];
__device__ int   g_top2i[ROWS];
__device__ float g_qupd[M * D];

// ---------------- scalar helpers ---------------------------------------------
__device__ __forceinline__ ull pack2(float lo, float hi) {
    ull r; asm("mov.b64 %0, {%1, %2};" : "=l"(r) : "f"(lo), "f"(hi)); return r;
}
__device__ __forceinline__ void unpack2(ull v, float& lo, float& hi) {
    asm("mov.b64 {%0, %1}, %2;" : "=f"(lo), "=f"(hi) : "l"(v));
}
__device__ __forceinline__ ull fma2(ull a, ull b, ull c) {
    ull d; asm("fma.rn.f32x2 %0, %1, %2, %3;" : "=l"(d) : "l"(a), "l"(b), "l"(c));
    return d;
}

// ---------------- K0a: keys transpose + zero qupd ------------------------------
__global__ __launch_bounds__(256) void k0a_init(const float* __restrict__ keys) {
    const int b = blockIdx.x;          // memory slot m
    const int t = threadIdx.x;         // d
    g_keysT[t * M + b] = keys[b * 256 + t];
    g_qupd[b * 256 + t] = 0.0f;
}

// ---------------- K0b: key norms -----------------------------------------------
__global__ __launch_bounds__(256) void k0b_norm(const float* __restrict__ keys) {
    __shared__ float rn[8];
    const int b = blockIdx.x, t = threadIdx.x;
    const int lane = t & 31, w = t >> 5;
    float kv = keys[b * 256 + t];
    float n2 = kv * kv;
#pragma unroll
    for (int off = 16; off > 0; off >>= 1) n2 += __shfl_xor_sync(0xffffffffu, n2, off);
    if (lane == 0) rn[w] = n2;
    __syncthreads();
    if (t == 0) {
        float tn = 0.0f;
#pragma unroll
        for (int i = 0; i < 8; ++i) tn += rn[i];
        g_knorm[b] = tn;
    }
}

// ---------------- K0c: key sums -------------------------------------------------
__global__ __launch_bounds__(256) void k0c_sum(const float* __restrict__ keys) {
    __shared__ float rs[8];
    const int b = blockIdx.x, t = threadIdx.x;
    const int lane = t & 31, w = t >> 5;
    float kv = keys[b * 256 + t];
#pragma unroll
    for (int off = 16; off > 0; off >>= 1) kv += __shfl_xor_sync(0xffffffffu, kv, off);
    if (lane == 0) rs[w] = kv;
    __syncthreads();
    if (t == 0) {
        float ts = 0.0f;
#pragma unroll
        for (int i = 0; i < 8; ++i) ts += rs[i];
        g_ksum[b] = ts;
    }
}

// ---------------- K1: blocked score GEMM + epilogue + blocked concat GEMM -----
// Thread tile: 8 rows x 8 cols. Warp: 4 rowgroups x 8 colgroups = 32 rows x 64.
// Score scores round-trip via SMEM [m][row(+pad)]; epilogue per-thread-row.
#define K1_SMEM (19264 * 4)   // tile 64x260 + qbuf 8x256 + wred 8x64 + bmaxs 64
__global__ __launch_bounds__(256, 2) void k1_score(const float* __restrict__ q,
                                                   const float* __restrict__ keys,
                                                   float* __restrict__ out_sm,
                                                   float* __restrict__ out_uq) {
    extern __shared__ float sdyn[];
    float* tile  = sdyn;            // [64][260] scores then P
    float* qbuf  = sdyn + 16640;    // [8][256]
    float* wred  = sdyn + 18688;    // [8][64]
    float* bmaxs = sdyn + 19200;    // [64]

    const int tid = threadIdx.x;
    const int lane = tid & 31, w = tid >> 5;
    const int rg = lane >> 3, cg = lane & 7;
    const int r0loc = w * 32 + rg * 8;
    const int rowbase = blockIdx.x * 256;
    const int R0 = rowbase + r0loc;
    const int row = rowbase + tid;
    const int rb4 = rowbase >> 2;

    // ---- blocked score GEMM ----
    ull acc[4][8];
#pragma unroll
    for (int p = 0; p < 4; ++p)
#pragma unroll
        for (int c = 0; c < 8; ++c) acc[p][c] = 0ull;

#pragma unroll 1
    for (int dc = 0; dc < 32; ++dc) {
        // stage q chunk (8 d x 256 rows) + free uq[:256] copy
#pragma unroll
        for (int it = 0; it < 2; ++it) {
            int idx = it * 256 + tid;
            int du = idx >> 6, seg = idx & 63;
            size_t g4 = (size_t)(dc * 8 + du) * (ROWS / 4) + rb4 + seg;
            float4 v = __ldg(&((const float4*)q)[g4]);
            ((float4*)qbuf)[idx] = v;
            __stcs(&((float4*)out_uq)[g4], v);
        }
        __syncthreads();
#pragma unroll
        for (int u = 0; u < 8; ++u) {
            const int d = dc * 8 + u;
            const ulonglong2* qr = (const ulonglong2*)(qbuf + u * 256 + r0loc);
            ulonglong2 qA = qr[0], qB = qr[1];   // (r0,r1),(r2,r3) / (r4,r5),(r6,r7)
            const float4* kk = (const float4*)(g_keysT + d * 64 + cg * 8);
            float4 ka = __ldg(kk), kb = __ldg(kk + 1);
            ull k2[8];
            k2[0] = pack2(ka.x, ka.x); k2[1] = pack2(ka.y, ka.y);
            k2[2] = pack2(ka.z, ka.z); k2[3] = pack2(ka.w, ka.w);
            k2[4] = pack2(kb.x, kb.x); k2[5] = pack2(kb.y, kb.y);
            k2[6] = pack2(kb.z, kb.z); k2[7] = pack2(kb.w, kb.w);
#pragma unroll
            for (int c = 0; c < 8; ++c) {
                acc[0][c] = fma2(qA.x, k2[c], acc[0][c]);
                acc[1][c] = fma2(qA.y, k2[c], acc[1][c]);
                acc[2][c] = fma2(qB.x, k2[c], acc[2][c]);
                acc[3][c] = fma2(qB.y, k2[c], acc[3][c]);
            }
        }
        __syncthreads();
    }

    // write scores to tile [m][row]
#pragma unroll
    for (int c = 0; c < 8; ++c)
#pragma unroll
        for (int p = 0; p < 4; ++p)
            *(ull*)(tile + (cg * 8 + c) * 260 + r0loc + 2 * p) = acc[p][c];
    __syncthreads();

    // ---- per-thread-row epilogue (row = rowbase + tid) ----
    float s[64];
#pragma unroll
    for (int m = 0; m < 64; ++m) s[m] = tile[m * 260 + tid];

    // top-2 (strict > keeps lowest index on ties, matching lax.top_k)
    float v1 = -1e30f, v2 = -1e30f; int i1 = 0, i2 = 0;
#pragma unroll
    for (int m = 0; m < 64; ++m) {
        float v = s[m];
        if (v > v1) { v2 = v1; i2 = i1; v1 = v; i1 = m; }
        else if (v > v2) { v2 = v; i2 = m; }
    }
    g_top1[row] = i1;
    g_top2i[row] = i2;
    g_sval[row] = v1;
    g_sval2[row] = v2;

    // block column-max partials
#pragma unroll
    for (int m = 0; m < 64; ++m) {
        float v = s[m];
        v = fmaxf(v, __shfl_xor_sync(0xffffffffu, v, 16));
        v = fmaxf(v, __shfl_xor_sync(0xffffffffu, v, 8));
        v = fmaxf(v, __shfl_xor_sync(0xffffffffu, v, 4));
        v = fmaxf(v, __shfl_xor_sync(0xffffffffu, v, 2));
        v = fmaxf(v, __shfl_xor_sync(0xffffffffu, v, 1));
        if (lane == 0) wred[w * 64 + m] = v;
    }
    __syncthreads();
    if (tid < 64) {
        float mx = wred[tid];
#pragma unroll
        for (int ww = 1; ww < 8; ++ww) mx = fmaxf(mx, wred[ww * 64 + tid]);
        bmaxs[tid] = mx;
        g_bmax[blockIdx.x * 64 + tid] = mx;
    }
    __syncthreads();

    // block column-sum partials w.r.t. block max
#pragma unroll
    for (int m = 0; m < 64; ++m) {
        float c = __expf(s[m] - bmaxs[m]);
        c += __shfl_xor_sync(0xffffffffu, c, 16);
        c += __shfl_xor_sync(0xffffffffu, c, 8);
        c += __shfl_xor_sync(0xffffffffu, c, 4);
        c += __shfl_xor_sync(0xffffffffu, c, 2);
        c += __shfl_xor_sync(0xffffffffu, c, 1);
        if (lane == 0) wred[w * 64 + m] = c;
    }
    __syncthreads();
    if (tid < 64) {
        float sm = 0.0f;
#pragma unroll
        for (int ww = 0; ww < 8; ++ww) sm += wred[ww * 64 + tid];
        g_bsum[blockIdx.x * 64 + tid] = sm;
    }

    // row softmax -> P
    float se = 0.0f;
#pragma unroll
    for (int m = 0; m < 64; ++m) { s[m] = __expf(s[m] - v1); se += s[m]; }
    g_se[row] = se;
    float inv = 1.0f / se;
#pragma unroll
    for (int m = 0; m < 64; ++m) s[m] *= inv;
#pragma unroll
    for (int j = 0; j < 16; ++j)
        ((float4*)(out_sm + (size_t)row * 64))[j] =
            make_float4(s[4 * j], s[4 * j + 1], s[4 * j + 2], s[4 * j + 3]);

    // P back into tile [m][row]
#pragma unroll
    for (int m = 0; m < 64; ++m) tile[m * 260 + tid] = s[m];
    __syncthreads();

    // ---- blocked concat GEMM: C[r][d] = sum_m P[r][m] * keys[m][d] ----
#pragma unroll 1
    for (int dt = 0; dt < 4; ++dt) {
        const int d0 = dt * 64 + cg * 8;
        ull a2[4][8];
#pragma unroll
        for (int p = 0; p < 4; ++p)
#pragma unroll
            for (int dd = 0; dd < 8; ++dd) a2[p][dd] = 0ull;

#pragma unroll 2
        for (int m = 0; m < 64; ++m) {
            const ulonglong2* pr = (const ulonglong2*)(tile + m * 260 + r0loc);
            ulonglong2 pA = pr[0], pB = pr[1];
            const float4* kk = (const float4*)(keys + m * 256 + d0);
            float4 ka = __ldg(kk), kb = __ldg(kk + 1);
            ull kd[8];
            kd[0] = pack2(ka.x, ka.x); kd[1] = pack2(ka.y, ka.y);
            kd[2] = pack2(ka.z, ka.z); kd[3] = pack2(ka.w, ka.w);
            kd[4] = pack2(kb.x, kb.x); kd[5] = pack2(kb.y, kb.y);
            kd[6] = pack2(kb.z, kb.z); kd[7] = pack2(kb.w, kb.w);
#pragma unroll
            for (int dd = 0; dd < 8; ++dd) {
                a2[0][dd] = fma2(pA.x, kd[dd], a2[0][dd]);
                a2[1][dd] = fma2(pA.y, kd[dd], a2[1][dd]);
                a2[2][dd] = fma2(pB.x, kd[dd], a2[2][dd]);
                a2[3][dd] = fma2(pB.y, kd[dd], a2[3][dd]);
            }
        }
#pragma unroll
        for (int dd = 0; dd < 8; ++dd)
#pragma unroll
            for (int p = 0; p < 4; ++p) {
                float lo, hi;
                unpack2(a2[p][dd], lo, hi);
                __stcs((float2*)&out_uq[(size_t)(256 + d0 + dd) * ROWS + R0 + 2 * p],
                       make_float2(lo, hi));
            }
    }
}

// ---------------- K2: combine per-block partials (256 blocks) -----------------
__global__ __launch_bounds__(256) void k2_combine() {   // grid 64 (one per m)
    __shared__ float red[256];
    const int m = blockIdx.x, t = threadIdx.x;
    float bm = g_bmax[t * 64 + m];
    red[t] = bm;
    __syncthreads();
#pragma unroll
    for (int s = 128; s > 0; s >>= 1) {
        if (t < s) red[t] = fmaxf(red[t], red[t + s]);
        __syncthreads();
    }
    float cmax = red[0];
    __syncthreads();
    red[t] = g_bsum[t * 64 + m] * __expf(bm - cmax);
    __syncthreads();
#pragma unroll
    for (int s = 128; s > 0; s >>= 1) {
        if (t < s) red[t] += red[t + s];
        __syncthreads();
    }
    if (t == 0) { g_cmax[m] = cmax; g_csum[m] = red[0]; }
}

// ---------------- K3: score_query reconstructed from score_memory -------------
__global__ __launch_bounds__(256) void k3_sq(const float* __restrict__ sm_in,
                                             float* __restrict__ out_sq) {
    __shared__ float cm[64], iv[64];
    const int tid = threadIdx.x;
    if (tid < 64) { cm[tid] = g_cmax[tid]; iv[tid] = 1.0f / g_csum[tid]; }
    __syncthreads();
    const float4* src = (const float4*)sm_in;
    float4* dst = (float4*)out_sq;
    const int base = blockIdx.x * 256 + tid;   // grid 1024 -> 262144 threads
#pragma unroll
    for (int r = 0; r < 4; ++r) {
        int i4 = base + r * 262144;
        int row = i4 >> 4;
        float v1 = __ldg(&g_sval[row]);
        float se = __ldg(&g_se[row]);
        int m0 = (i4 << 2) & 63;
        float4 v = src[i4];
        float4 o;
        o.x = v.x * se * __expf(v1 - cm[m0])     * iv[m0];
        o.y = v.y * se * __expf(v1 - cm[m0 + 1]) * iv[m0 + 1];
        o.z = v.z * se * __expf(v1 - cm[m0 + 2]) * iv[m0 + 2];
        o.w = v.w * se * __expf(v1 - cm[m0 + 3]) * iv[m0 + 3];
        __stcs(&dst[i4], o);
    }
}

// ---------------- K4f: gathering_loss + spreading + query_update scatter ------
__global__ __launch_bounds__(256, 2) void k4_fused(const float* __restrict__ q,
                                                   const float* __restrict__ keys,
                                                   float* __restrict__ out_gl,
                                                   float* __restrict__ out_sp) {
    __shared__ float tile[256 * 33];   // [d][r]
    __shared__ int   gi[32];
    __shared__ float swgt[32];
    __shared__ float scm[64], skn[64], sks[64];
    __shared__ float pnq[8 * 32], psm[8 * 32];

    const int tid = threadIdx.x;
    const int lane = tid & 31, w = tid >> 5;
    const int rowbase = blockIdx.x * 128;

    if (tid < 64) { scm[tid] = g_cmax[tid]; skn[tid] = g_knorm[tid]; sks[tid] = g_ksum[tid]; }

    float acc[8][8];
#pragma unroll
    for (int mi = 0; mi < 8; ++mi)
#pragma unroll
        for (int i = 0; i < 8; ++i) acc[mi][i] = 0.0f;

    for (int c = 0; c < 4; ++c) {
        const int row0 = rowbase + c * 32;
        __syncthreads();   // previous chunk done; scm/skn/sks ready (c==0)
        if (tid < 32) {
            int g = g_top1[row0 + tid];
            gi[tid] = g;
            swgt[tid] = __expf(g_sval[row0 + tid] - scm[g]);
        }
        // phase A: load q chunk + per-thread nq2/sumq partials
        {
            const int r = lane, dg = w;
            float nqp = 0.0f, smp = 0.0f;
#pragma unroll 8
            for (int it = 0; it < 32; ++it) {
                int d = it * 8 + dg;
                float qv = q[(size_t)d * ROWS + row0 + r];
                tile[d * 33 + r] = qv;
                nqp = fmaf(qv, qv, nqp);
                smp += qv;
            }
            pnq[dg * 32 + r] = nqp;
            psm[dg * 32 + r] = smp;
        }
        __syncthreads();

        // spreading loss via algebraic identity (lanes 0-31 only)
        if (tid < 32) {
            float nq2 = 0.0f, sq = 0.0f;
#pragma unroll
            for (int g8 = 0; g8 < 8; ++g8) { nq2 += pnq[g8 * 32 + tid]; sq += psm[g8 * 32 + tid]; }
            int rrow = row0 + tid;
            int i1 = gi[tid], i2 = g_top2i[rrow];
            float v1 = g_sval[rrow], v2 = g_sval2[rrow];
            const float e = 1e-6f;
            float dp2 = nq2 - 2.0f * v1 + skn[i1] + 2.0f * e * (sq - sks[i1]) + 256.0f * e * e;
            float dn2 = nq2 - 2.0f * v2 + skn[i2] + 2.0f * e * (sq - sks[i2]) + 256.0f * e * e;
            out_sp[rrow] = fmaxf(sqrtf(fmaxf(dp2, 0.0f)) - sqrtf(fmaxf(dn2, 0.0f)) + 1.0f, 0.0f);
        }

        // phase B: gathering_loss (d = tid, coalesced)
        {
            const int d = tid;
#pragma unroll 4
            for (int it = 0; it < 32; ++it) {
                int g = gi[it];
                float qv = tile[d * 33 + it];
                float kp = __ldg(&keys[g * 256 + d]);
                float df = qv - kp;
                __stcs(&out_gl[(size_t)(row0 + it) * 256 + d], df * df);
            }
        }

        // phase C: warp-owned scatter-reduce into registers
        for (int r = 0; r < 32; ++r) {
            int g = gi[r];
            if ((g >> 3) == w) {
                float wv = swgt[r];
#pragma unroll
                for (int mi = 0; mi < 8; ++mi) {
                    if (g == w * 8 + mi) {
#pragma unroll
                        for (int i = 0; i < 8; ++i)
                            acc[mi][i] += wv * tile[(lane + 32 * i) * 33 + r];
                    }
                }
            }
        }
    }

    // epilogue: one global reduce per (m, d)
#pragma unroll
    for (int mi = 0; mi < 8; ++mi)
#pragma unroll
        for (int i = 0; i < 8; ++i)
            atomicAdd(&g_qupd[(w * 8 + mi) * 256 + lane + 32 * i], acc[mi][i]);
}

// ---------------- K7: updated_memory = normalize(qupd + keys) -----------------
__global__ __launch_bounds__(256) void k7_um(const float* __restrict__ keys,
                                             float* __restrict__ out_um) {
    __shared__ float wr[8];
    const int m = blockIdx.x, d = threadIdx.x;
    const int lane = d & 31, w = d >> 5;
    float val = g_qupd[m * 256 + d] + keys[m * 256 + d];
    float ss = val * val;
#pragma unroll
    for (int off = 16; off > 0; off >>= 1) ss += __shfl_xor_sync(0xffffffffu, ss, off);
    if (lane == 0) wr[w] = ss;
    __syncthreads();
    float tot = 0.0f;
#pragma unroll
    for (int i = 0; i < 8; ++i) tot += wr[i];
    float n = sqrtf(tot);
    float denom = fmaxf(n, 1e-12f);
    out_um[m * 256 + d] = val / denom;
}

// ---------------- launch -------------------------------------------------------
extern "C" void kernel_launch(void* const* d_in, const int* in_sizes, int n_in,
                              void* d_out, int out_size) {
    const float* query = (const float*)d_in[0];   // (256, 1024, 64)
    const float* keys  = (const float*)d_in[1];   // (64, 256)
    float* out = (float*)d_out;

    cudaFuncSetAttribute(k1_score, cudaFuncAttributeMaxDynamicSharedMemorySize, K1_SMEM);

    k0a_init<<<64, 256>>>(keys);
    k0b_norm<<<64, 256>>>(keys);
    k0c_sum<<<64, 256>>>(keys);
    k1_score<<<256, 256, K1_SMEM>>>(query, keys, out + OFF_SM, out + OFF_UQ);
    k2_combine<<<64, 256>>>();
    k3_sq<<<1024, 256>>>(out + OFF_SM, out + OFF_SQ);
    k4_fused<<<512, 256>>>(query, keys, out + OFF_GL, out + OFF_SP);
    k7_um<<<64, 256>>>(keys, out + OFF_UM);
}